// round 6
// baseline (speedup 1.0000x reference)
#include <cuda_runtime.h>
#include <math.h>
#include <stdint.h>

// ---------------- constants ----------------
#define NCc 128
#define NTc 256
// padded strides: phase1 (H=256,W=128): XS=160, GS=136 ; phase2 (H=128,W=256): XS=288, GS=264
#define RSTR 264          // refine padded row stride (4 zero guards each side)
#define RCH  33792        // 128*264 per refine channel

// ---------------- scratch (static device memory; no allocations) ----------------
__device__ float g_X[655360];     // activations [H][16][XS] (padded)
__device__ float g_SKIP[655360];  // skip accumulator, same layout
__device__ float g_G[278528];     // gated intermediate [H][8][GS] (padded)
__device__ float g_R2[524288];    // stage-C intermediate [f(16)][m(128)][t(256)]
__device__ float g_HINP[524288];  // hinp  [c(128)][f(16)][t(256)]
__device__ float g_HFT[1048576];  // hout_ft [g(32)][c(128)][u(256)]
__device__ float g_RA[2162688];   // refine ping [ch(64)][c(128)][RSTR]
__device__ float g_RB[2162688];   // refine pong
__device__ unsigned g_FN;         // fnorm bits

__device__ __forceinline__ float dfh_tanh(float x){ return tanhf(x)*0.98f + 0.02f*x; }
__device__ __forceinline__ float dfh_sig (float x){ return 0.98f/(1.0f+expf(-x)) + 0.02f*x; }

// ---------------- packed f32x2 helpers ----------------
__device__ __forceinline__ void fma2(uint64_t &d, uint64_t a, uint64_t b){
    asm("fma.rn.f32x2 %0, %1, %2, %0;" : "+l"(d) : "l"(a), "l"(b));
}
__device__ __forceinline__ uint64_t pack2(float x){
    uint64_t r; asm("mov.b64 %0, {%1, %1};" : "=l"(r) : "f"(x)); return r;
}
__device__ __forceinline__ float2 unpack2(uint64_t v){
    float2 f; asm("mov.b64 {%0, %1}, %2;" : "=f"(f.x), "=f"(f.y) : "l"(v)); return f;
}

// ---------------- zero helpers ----------------
__global__ void k_zero3()
{
    int stride = gridDim.x*blockDim.x;
    for (int i = blockIdx.x*blockDim.x + threadIdx.x; i < 655360; i += stride) {
        g_X[i] = 0.0f; g_SKIP[i] = 0.0f;
        if (i < 278528) g_G[i] = 0.0f;
    }
}
__global__ void k_zeroref()
{
    int stride = gridDim.x*blockDim.x;
    for (int i = blockIdx.x*blockDim.x + threadIdx.x; i < 2162688; i += stride) {
        g_RA[i] = 0.0f; g_RB[i] = 0.0f;
    }
}

// ---------------- input dense (4->16) ----------------
__global__ void k_dense1(const float* __restrict__ inc, const float* __restrict__ icc,
                         const float* __restrict__ times, const float* __restrict__ tin,
                         const float* __restrict__ cw, const float* __restrict__ cb)
{
    int t = blockIdx.x, c = threadIdx.x;  // 256 x 128
    float i0 = inc[c*NTc + t];
    float i1 = icc[c*NTc + t];
    float i2 = times[t];
    float i3 = tin[c];
    #pragma unroll
    for (int o = 0; o < 16; ++o) {
        float v = i0*cw[o] + i1*cw[16+o] + i2*cw[32+o] + i3*cw[48+o] + cb[o];
        g_X[(t*16+o)*160 + c] = dfh_tanh(v);
    }
}

// ---------------- wave layer: gated dilated conv pair (16ch -> 4+4 outs/block) ----------------
// grid = 256: pb = bid>>1, half = bid&1 -> outputs o0..o0+3 of each conv
__global__ __launch_bounds__(256) void k_conv12(
    const float* __restrict__ w1g, const float* __restrict__ b1,
    const float* __restrict__ w2g, const float* __restrict__ b2,
    int H, int W, int XS, int GS, int dil)
{
    __shared__ float4 sW[1280];   // [tap(40)][ci(16)][conv(2)] -> 4 outs
    int half = blockIdx.x & 1;
    int pb   = blockIdx.x >> 1;
    int o0 = half*4;
    for (int i = threadIdx.x; i < 1280; i += 256) {
        int tap = i >> 5, ci = (i >> 1) & 15, which = i & 1;
        const float* src = (which ? w2g : w1g) + tap*128 + ci*8 + o0;
        sW[i] = *(const float4*)src;
    }
    __syncthreads();
    int lane = threadIdx.x & 31, warp = threadIdx.x >> 5;
    int chunks = W >> 5;
    int r = warp / chunks, q = warp - r*chunks;
    int w = (q << 5) + lane;
    int h = pb * (8 / chunks) + r;

    uint64_t accA[4] = {0,0,0,0};   // ci 0..7
    uint64_t accB[4] = {0,0,0,0};   // ci 8..15

    for (int kh = 0; kh < 5; ++kh) {
        int hh = h + kh - 2;
        if ((unsigned)hh >= (unsigned)H) continue;
        const float* xrow = g_X + hh*16*XS;
        for (int kw = 0; kw < 8; ++kw) {
            int cb0 = (q << 5) + kw*dil;
            if (cb0 >= W) break;               // warp-uniform
            const float* xp = xrow + cb0 + lane;   // pad makes per-lane read safe
            const ulonglong2* wp = (const ulonglong2*)(sW + (kh*8+kw)*32);
            #pragma unroll
            for (int ci = 0; ci < 16; ++ci) {
                uint64_t* ac = (ci < 8) ? accA : accB;
                uint64_t xv2 = pack2(__ldg(xp + ci*XS));
                ulonglong2 wv1 = wp[2*ci];     // conv1 pairs (o0,o1),(o2,o3)
                ulonglong2 wv2 = wp[2*ci+1];   // conv2 pairs
                fma2(ac[0], xv2, wv1.x); fma2(ac[1], xv2, wv1.y);
                fma2(ac[2], xv2, wv2.x); fma2(ac[3], xv2, wv2.y);
            }
        }
    }
    float y1[4], y2[4];
    {
        float2 a0 = unpack2(accA[0]), b0 = unpack2(accB[0]);
        float2 a1 = unpack2(accA[1]), b1v = unpack2(accB[1]);
        y1[0]=a0.x+b0.x; y1[1]=a0.y+b0.y; y1[2]=a1.x+b1v.x; y1[3]=a1.y+b1v.y;
        float2 a2 = unpack2(accA[2]), b2v = unpack2(accB[2]);
        float2 a3 = unpack2(accA[3]), b3 = unpack2(accB[3]);
        y2[0]=a2.x+b2v.x; y2[1]=a2.y+b2v.y; y2[2]=a3.x+b3.x; y2[3]=a3.y+b3.y;
    }
    #pragma unroll
    for (int j = 0; j < 4; ++j) {
        int oo = o0 + j;
        float g = dfh_tanh(y1[j] + __ldg(b1+oo)) * dfh_sig(y2[j] + __ldg(b2+oo));
        g_G[(h*8+oo)*GS + w] = g;
    }
}

// ---------------- wave layer: z conv (8ch -> 8 of 16 outs/block) ----------------
// grid = 256: pb = bid>>1, half = bid&1
__global__ __launch_bounds__(256) void k_convz(
    const float* __restrict__ wzg, const float* __restrict__ bz,
    int H, int W, int XS, int GS)
{
    __shared__ float4 sW[640];  // [tap(40)][ci(8)][2] -> 8 outs
    int half = blockIdx.x & 1;
    int pb   = blockIdx.x >> 1;
    int o0 = half * 8;
    for (int i = threadIdx.x; i < 640; i += 256) {
        int tap = i >> 4, ci = (i >> 1) & 7, part = i & 1;
        sW[i] = *(const float4*)(wzg + tap*128 + ci*16 + o0 + part*4);
    }
    __syncthreads();
    int lane = threadIdx.x & 31, warp = threadIdx.x >> 5;
    int chunks = W >> 5;
    int r = warp / chunks, q = warp - r*chunks;
    int w = (q << 5) + lane;
    int h = pb * (8 / chunks) + r;

    uint64_t accA[4] = {0,0,0,0};   // ci 0..3
    uint64_t accB[4] = {0,0,0,0};   // ci 4..7

    for (int kh = 0; kh < 5; ++kh) {
        int hh = h + kh - 2;
        if ((unsigned)hh >= (unsigned)H) continue;
        const float* grow = g_G + hh*8*GS + w;
        #pragma unroll
        for (int kw = 0; kw < 8; ++kw) {
            const float* xp = grow + kw;              // pad: no guard
            const ulonglong2* wp = (const ulonglong2*)(sW + (kh*8+kw)*16);
            #pragma unroll
            for (int ci = 0; ci < 8; ++ci) {
                uint64_t* ac = (ci < 4) ? accA : accB;
                uint64_t xv2 = pack2(__ldg(xp + ci*GS));
                ulonglong2 w01 = wp[2*ci];
                ulonglong2 w23 = wp[2*ci+1];
                fma2(ac[0], xv2, w01.x); fma2(ac[1], xv2, w01.y);
                fma2(ac[2], xv2, w23.x); fma2(ac[3], xv2, w23.y);
            }
        }
    }
    #pragma unroll
    for (int p = 0; p < 4; ++p) {
        float2 va = unpack2(accA[p]);
        float2 vb = unpack2(accB[p]);
        int oo = o0 + 2*p;
        float z0 = va.x + vb.x + __ldg(bz+oo);
        float z1 = va.y + vb.y + __ldg(bz+oo+1);
        int idx0 = (h*16+oo)*XS + w;
        int idx1 = idx0 + XS;
        g_SKIP[idx0] += z0;  g_X[idx0] += z0;
        g_SKIP[idx1] += z1;  g_X[idx1] += z1;
    }
}

// ---------------- stage C1: 128-pt DFT over channel axis ----------------
__global__ void k_c1()
{
    int t = blockIdx.x, f = blockIdx.y;     // 256 x 16
    __shared__ float vr[64], vi[64], tc[128], ts[128];
    int tid = threadIdx.x;                  // 128
    if (tid < 64) {
        int k = tid;
        float cr = g_SKIP[(t*16+f)*160 + 2*k];
        float ci = g_SKIP[(t*16+f)*160 + 2*k+1];
        cr = dfh_tanh(cr); ci = dfh_tanh(ci);
        float s = ((k==0)?0.5f:1.0f) * ((k&1)?-1.0f:1.0f);
        vr[k] = s*cr; vi[k] = s*ci;
    }
    {
        float sv, cv; sincospif((float)tid * (1.0f/64.0f), &sv, &cv);
        tc[tid] = cv; ts[tid] = sv;
    }
    __syncthreads();
    int m = tid;
    float acc = 0.0f;
    #pragma unroll 8
    for (int k = 0; k < 64; ++k) {
        int j = (k*m) & 127;
        acc += vr[k]*tc[j] + vi[k]*ts[j];
    }
    g_R2[(f*128+m)*NTc + t] = acc;
}

// ---------------- stage C2: 256-pt real DFT; Hilbert chain collapsed ----------------
__global__ void k_c2(const float* __restrict__ times)
{
    int m = blockIdx.x, f = blockIdx.y;     // 128 x 16
    __shared__ float v[256], tc[256], ts[256];
    int tid = threadIdx.x;                  // 128
    v[tid]       = g_R2[(f*128+m)*NTc + tid];
    v[tid+128]   = g_R2[(f*128+m)*NTc + tid + 128];
    {
        float sv, cv;
        sincospif((float)tid * (1.0f/128.0f), &sv, &cv);        tc[tid] = cv;      ts[tid] = sv;
        sincospif((float)(tid+128) * (1.0f/128.0f), &sv, &cv);  tc[tid+128] = cv;  ts[tid+128] = sv;
    }
    __syncthreads();
    int k = tid;
    float zm = (k==0) ? 1.0f : ((fabsf(times[2*k]) > 0.0f) ? 1.0f : 0.0f);
    float scale = zm * ((k&1)?-1.0f:1.0f) * (1.0f/128.0f);
    float ar = 0.0f, ai = 0.0f;
    #pragma unroll 8
    for (int t = 0; t < 256; ++t) {
        int j = (t*k) & 255;
        ar += v[t]*tc[j];
        ai += v[t]*ts[j];
    }
    g_HINP[(m*16+f)*NTc + 2*k]   = scale*ar;
    g_HINP[(m*16+f)*NTc + 2*k+1] = scale*ai;
}

// ---------------- dense2 (16->16) ----------------
__global__ void k_dense2(const float* __restrict__ hw, const float* __restrict__ hb)
{
    int c = blockIdx.x;       // 128
    int t = threadIdx.x;      // 256
    float in[16];
    #pragma unroll
    for (int f = 0; f < 16; ++f) in[f] = g_HINP[(c*16+f)*NTc + t];
    #pragma unroll
    for (int o = 0; o < 16; ++o) {
        float acc = hb[o];
        #pragma unroll
        for (int f = 0; f < 16; ++f) acc += in[f]*hw[f*16+o];
        g_X[(c*16+o)*288 + t] = dfh_tanh(acc);
    }
}

// ---------------- stage D: hout_ft via 256-pt DFT ----------------
__global__ void k_stageD()
{
    int c = blockIdx.x, g = blockIdx.y;     // 128 x 32
    __shared__ float hr[128], hi[128], tc[256], ts[256];
    int tid = threadIdx.x;                  // 256
    if (tid < 128) {
        int j = tid;
        float v0, v1;
        if (g < 16) {
            float a = g_SKIP[(c*16+g)*288 + 2*j];   v0 = dfh_tanh(a);
            float b = g_SKIP[(c*16+g)*288 + 2*j+1]; v1 = dfh_tanh(b);
        } else {
            v0 = g_HINP[(c*16+(g-16))*NTc + 2*j];
            v1 = g_HINP[(c*16+(g-16))*NTc + 2*j+1];
        }
        float s = ((j==0)?0.5f:1.0f) * ((j&1)?-1.0f:1.0f);
        hr[j] = s*v0; hi[j] = s*v1;
    }
    {
        float sv, cv; sincospif((float)tid * (1.0f/128.0f), &sv, &cv);
        tc[tid] = cv; ts[tid] = sv;
    }
    __syncthreads();
    int u = tid;
    float acc = 0.0f;
    #pragma unroll 8
    for (int j = 0; j < 128; ++j) {
        int idx = (j*u) & 255;
        acc += hr[j]*tc[idx] + hi[j]*ts[idx];
    }
    g_HFT[(g*128+c)*NTc + u] = acc;
}

// ---------------- fnorm reduction ----------------
__global__ void k_fninit(){ g_FN = 0u; }

__global__ void k_fnred()
{
    int stride = gridDim.x*blockDim.x;
    float mx = 0.0f;
    for (int i = blockIdx.x*blockDim.x + threadIdx.x; i < 1048576; i += stride)
        mx = fmaxf(mx, fabsf(g_HFT[i]));
    #pragma unroll
    for (int o = 16; o; o >>= 1) mx = fmaxf(mx, __shfl_xor_sync(0xFFFFFFFFu, mx, o));
    __shared__ float sm[8];
    int lane = threadIdx.x & 31, warp = threadIdx.x >> 5;
    if (lane == 0) sm[warp] = mx;
    __syncthreads();
    if (warp == 0) {
        mx = (lane < 8) ? sm[lane] : 0.0f;
        #pragma unroll
        for (int o = 4; o; o >>= 1) mx = fmaxf(mx, __shfl_xor_sync(0xFFFFFFFFu, mx, o));
        if (lane == 0) atomicMax(&g_FN, __float_as_uint(mx));
    }
}

__global__ void k_refinit()
{
    float inv = 1.0f/__uint_as_float(g_FN);
    int c = blockIdx.x;     // 128
    int u = threadIdx.x;    // 256
    #pragma unroll 4
    for (int ch = 0; ch < 64; ++ch)
        g_RA[ch*RCH + c*RSTR + 4 + u] = g_HFT[(ch & 31)*32768 + c*256 + u] * inv;
}

// ---------------- refine conv: SAME 9x9, 64ch -> 8 of 32 outs/block ----------------
// grid = 512: c = bid>>2, osel = bid&3
__global__ __launch_bounds__(256) void k_refconv(
    const float* __restrict__ Wg, const float* __restrict__ Bg,
    int obase, int actType, int swap)
{
    const float* RIN  = swap ? g_RB : g_RA;
    float*       ROUT = swap ? g_RA : g_RB;
    int c    = blockIdx.x >> 2;
    int osel = blockIdx.x & 3;
    int o0   = osel * 8;
    int u    = threadIdx.x;       // 256
    __shared__ float4 sw[1152];   // per-kh stage: [kw(9)][ci(64)][2]

    uint64_t accA[4] = {0,0,0,0};   // ci 0..31
    uint64_t accB[4] = {0,0,0,0};   // ci 32..63

    for (int kh = 0; kh < 9; ++kh) {
        __syncthreads();
        const float* wbase = Wg + (kh*9)*2048 + o0;
        for (int i = threadIdx.x; i < 1152; i += 256) {
            int kwci = i >> 1, part = i & 1;
            sw[i] = *(const float4*)(wbase + kwci*32 + part*4);
        }
        __syncthreads();

        int cc = c + kh - 4;
        if ((unsigned)cc >= 128u) continue;      // block-uniform
        const float* rowp = RIN + cc*RSTR + u;   // +4 pad merged with kw-4
        for (int kw = 0; kw < 9; ++kw) {
            const float* xp = rowp + kw;         // no guard: zero pad
            const ulonglong2* wp = (const ulonglong2*)(sw + kw*128);
            #pragma unroll 8
            for (int ci = 0; ci < 64; ++ci) {
                uint64_t* ac = (ci < 32) ? accA : accB;
                uint64_t xv2 = pack2(__ldg(xp + ci*RCH));
                ulonglong2 w0 = wp[2*ci];
                ulonglong2 w1 = wp[2*ci+1];
                fma2(ac[0], xv2, w0.x); fma2(ac[1], xv2, w0.y);
                fma2(ac[2], xv2, w1.x); fma2(ac[3], xv2, w1.y);
            }
        }
    }
    int pos = c*RSTR + 4 + u;
    #pragma unroll
    for (int p = 0; p < 4; ++p) {
        float2 va = unpack2(accA[p]);
        float2 vb = unpack2(accB[p]);
        float vv[2] = {va.x + vb.x, va.y + vb.y};
        #pragma unroll
        for (int s = 0; s < 2; ++s) {
            int k = o0 + 2*p + s;
            float v = vv[s] + __ldg(Bg + k);
            float a;
            if (actType == 0) a = dfh_tanh(v);
            else              a = (v > 0.0f ? v : 0.0f)*0.98f + 0.02f*v;
            int ch = obase + k;
            ROUT[ch*RCH + pos] = a + RIN[ch*RCH + pos];
        }
    }
}

// ---------------- final dense (96 -> 2) ----------------
__global__ void k_final(const float* __restrict__ dw, const float* __restrict__ db,
                        float* __restrict__ out)
{
    int c = blockIdx.x;     // 128
    int u = threadIdx.x;    // 256
    int rpos = c*RSTR + 4 + u;
    int hpos = c*256 + u;
    float fn = __uint_as_float(g_FN);
    float a0 = __ldg(db), a1 = __ldg(db+1);
    #pragma unroll 8
    for (int p = 0; p < 64; ++p) {
        float v = g_RA[p*RCH + rpos] * fn;
        a0 += v*__ldg(dw + 2*p);
        a1 += v*__ldg(dw + 2*p + 1);
    }
    #pragma unroll 8
    for (int q = 0; q < 32; ++q) {
        float v = g_HFT[q*32768 + hpos];
        a0 += v*__ldg(dw + 2*(64+q));
        a1 += v*__ldg(dw + 2*(64+q) + 1);
    }
    out[hpos*2]     = a0;
    out[hpos*2 + 1] = a1/fn;
}

// ---------------- launch ----------------
extern "C" void kernel_launch(void* const* d_in, const int* in_sizes, int n_in,
                              void* d_out, int out_size)
{
    const float* times    = (const float*)d_in[0];
    const float* times_in = (const float*)d_in[1];
    const float* inp_nc   = (const float*)d_in[2];
    const float* inp_c    = (const float*)d_in[3];
    const float* cdw  = (const float*)d_in[4];
    const float* cdb  = (const float*)d_in[5];
    const float* cwy1 = (const float*)d_in[6];
    const float* cby1 = (const float*)d_in[7];
    const float* cwy2 = (const float*)d_in[8];
    const float* cby2 = (const float*)d_in[9];
    const float* cwz0 = (const float*)d_in[10];
    const float* cbz0 = (const float*)d_in[11];
    const float* hdw  = (const float*)d_in[12];
    const float* hdb  = (const float*)d_in[13];
    const float* hwy1 = (const float*)d_in[14];
    const float* hby1 = (const float*)d_in[15];
    const float* hwy2 = (const float*)d_in[16];
    const float* hby2 = (const float*)d_in[17];
    const float* hwz0 = (const float*)d_in[18];
    const float* hbz0 = (const float*)d_in[19];
    const float* rwr  = (const float*)d_in[20];
    const float* rbr  = (const float*)d_in[21];
    const float* rwt  = (const float*)d_in[22];
    const float* rbt  = (const float*)d_in[23];
    const float* dw   = (const float*)d_in[24];
    const float* db   = (const float*)d_in[25];
    float* out = (float*)d_out;

    static const int DILS[15] = {1,2,3,4,6,8,10,12,14,16,18,20,24,28,32};

    // ---- fidnet 1: H=256, W=128, XS=160, GS=136 ----
    k_zero3<<<512,256>>>();
    k_dense1<<<256,128>>>(inp_nc, inp_c, times, times_in, cdw, cdb);
    for (int i = 0; i < 45; ++i) {
        int d = DILS[i % 15];
        k_conv12<<<256,256>>>(cwy1 + i*5120, cby1 + i*8, cwy2 + i*5120, cby2 + i*8,
                              256, 128, 160, 136, d);
        k_convz <<<256,256>>>(cwz0 + i*5120, cbz0 + i*16, 256, 128, 160, 136);
    }

    // ---- spectral glue ----
    k_c1<<<dim3(256,16),128>>>();
    k_c2<<<dim3(128,16),128>>>(times);

    // ---- fidnet 2: H=128, W=256, XS=288, GS=264 ----
    k_zero3<<<512,256>>>();
    k_dense2<<<128,256>>>(hdw, hdb);
    for (int i = 0; i < 45; ++i) {
        int d = DILS[i % 15];
        k_conv12<<<256,256>>>(hwy1 + i*5120, hby1 + i*8, hwy2 + i*5120, hby2 + i*8,
                              128, 256, 288, 264, d);
        k_convz <<<256,256>>>(hwz0 + i*5120, hbz0 + i*16, 128, 256, 288, 264);
    }

    // ---- hout_ft ----
    k_stageD<<<dim3(128,32),256>>>();

    // ---- fnorm + refine ----
    k_fninit<<<1,1>>>();
    k_fnred<<<256,256>>>();
    k_zeroref<<<512,256>>>();
    k_refinit<<<128,256>>>();
    for (int i = 0; i < 4; ++i) {
        k_refconv<<<512,256>>>(rwt + i*165888, rbt + i*32, 0,  0, i & 1);
        k_refconv<<<512,256>>>(rwr + i*165888, rbr + i*32, 32, 1, i & 1);
    }

    // ---- final dense + output ----
    k_final<<<128,256>>>(dw, db, out);
}

// round 7
// speedup vs baseline: 1.5765x; 1.5765x over previous
#include <cuda_runtime.h>
#include <math.h>
#include <stdint.h>

// ---------------- constants ----------------
#define NCc 128
#define NTc 256
#define RSTR 264          // refine padded row stride (4 zero guards each side)
#define RCH  33792        // 128*264 per refine channel

// ---------------- scratch ----------------
__device__ float g_X[655360];     // activations [H][16][XS] (padded)
__device__ float g_SKIP[655360];  // skip accumulator
__device__ float g_G[278528];     // gated intermediate [H][8][GS] (padded)
__device__ float g_R2[524288];    // [f(16)][m(128)][t(256)]
__device__ float g_HINP[524288];  // [c(128)][f(16)][t(256)]
__device__ float g_HFT[1048576];  // [g(32)][c(128)][u(256)]
__device__ float g_RA[2162688];   // refine ping [ch(64)][c(128)][RSTR]
__device__ float g_RB[2162688];   // refine pong
__device__ unsigned g_FN;

__device__ __forceinline__ float dfh_tanh(float x){ return tanhf(x)*0.98f + 0.02f*x; }
__device__ __forceinline__ float dfh_sig (float x){ return 0.98f/(1.0f+expf(-x)) + 0.02f*x; }

// ---------------- packed f32x2 helpers ----------------
__device__ __forceinline__ void fma2(uint64_t &d, uint64_t a, uint64_t b){
    asm("fma.rn.f32x2 %0, %1, %2, %0;" : "+l"(d) : "l"(a), "l"(b));
}
__device__ __forceinline__ uint64_t pack2(float x){
    uint64_t r; asm("mov.b64 %0, {%1, %1};" : "=l"(r) : "f"(x)); return r;
}
__device__ __forceinline__ float2 unpack2(uint64_t v){
    float2 f; asm("mov.b64 {%0, %1}, %2;" : "=f"(f.x), "=f"(f.y) : "l"(v)); return f;
}

// ---------------- zero helpers ----------------
__global__ void k_zero3()
{
    int stride = gridDim.x*blockDim.x;
    for (int i = blockIdx.x*blockDim.x + threadIdx.x; i < 655360; i += stride) {
        g_X[i] = 0.0f; g_SKIP[i] = 0.0f;
        if (i < 278528) g_G[i] = 0.0f;
    }
}
__global__ void k_zeroref()
{
    int stride = gridDim.x*blockDim.x;
    for (int i = blockIdx.x*blockDim.x + threadIdx.x; i < 2162688; i += stride) {
        g_RA[i] = 0.0f; g_RB[i] = 0.0f;
    }
}

// ---------------- input dense (4->16) ----------------
__global__ void k_dense1(const float* __restrict__ inc, const float* __restrict__ icc,
                         const float* __restrict__ times, const float* __restrict__ tin,
                         const float* __restrict__ cw, const float* __restrict__ cb)
{
    int t = blockIdx.x, c = threadIdx.x;  // 256 x 128
    float i0 = inc[c*NTc + t];
    float i1 = icc[c*NTc + t];
    float i2 = times[t];
    float i3 = tin[c];
    #pragma unroll
    for (int o = 0; o < 16; ++o) {
        float v = i0*cw[o] + i1*cw[16+o] + i2*cw[32+o] + i3*cw[48+o] + cb[o];
        g_X[(t*16+o)*160 + c] = dfh_tanh(v);
    }
}

// ---------------- wave layer: gated dilated conv pair (16ch -> 4+4 outs/block) ----------------
__global__ __launch_bounds__(256) void k_conv12(
    const float* __restrict__ w1g, const float* __restrict__ b1,
    const float* __restrict__ w2g, const float* __restrict__ b2,
    int H, int W, int XS, int GS, int dil)
{
    __shared__ float4 sW[1280];   // [tap(40)][ci(16)][conv(2)]
    int half = blockIdx.x & 1;
    int pb   = blockIdx.x >> 1;
    int o0 = half*4;
    for (int i = threadIdx.x; i < 1280; i += 256) {
        int tap = i >> 5, ci = (i >> 1) & 15, which = i & 1;
        const float* src = (which ? w2g : w1g) + tap*128 + ci*8 + o0;
        sW[i] = *(const float4*)src;
    }
    __syncthreads();
    int lane = threadIdx.x & 31, warp = threadIdx.x >> 5;
    int chunks = W >> 5;
    int r = warp / chunks, q = warp - r*chunks;
    int w = (q << 5) + lane;
    int h = pb * (8 / chunks) + r;

    uint64_t accA[4] = {0,0,0,0};   // ci 0..7
    uint64_t accB[4] = {0,0,0,0};   // ci 8..15

    for (int kh = 0; kh < 5; ++kh) {
        int hh = h + kh - 2;
        if ((unsigned)hh >= (unsigned)H) continue;
        const float* xrow = g_X + hh*16*XS;
        for (int kw = 0; kw < 8; ++kw) {
            int cb0 = (q << 5) + kw*dil;
            if (cb0 >= W) break;               // warp-uniform
            const float* xp = xrow + cb0 + lane;
            const ulonglong2* wp = (const ulonglong2*)(sW + (kh*8+kw)*32);
            #pragma unroll
            for (int ci = 0; ci < 8; ++ci) {
                uint64_t xv2 = pack2(__ldg(xp + ci*XS));
                ulonglong2 wv1 = wp[2*ci];
                ulonglong2 wv2 = wp[2*ci+1];
                fma2(accA[0], xv2, wv1.x); fma2(accA[1], xv2, wv1.y);
                fma2(accA[2], xv2, wv2.x); fma2(accA[3], xv2, wv2.y);
            }
            #pragma unroll
            for (int ci = 8; ci < 16; ++ci) {
                uint64_t xv2 = pack2(__ldg(xp + ci*XS));
                ulonglong2 wv1 = wp[2*ci];
                ulonglong2 wv2 = wp[2*ci+1];
                fma2(accB[0], xv2, wv1.x); fma2(accB[1], xv2, wv1.y);
                fma2(accB[2], xv2, wv2.x); fma2(accB[3], xv2, wv2.y);
            }
        }
    }
    float y1[4], y2[4];
    {
        float2 a0 = unpack2(accA[0]), b0 = unpack2(accB[0]);
        float2 a1 = unpack2(accA[1]), b1v = unpack2(accB[1]);
        y1[0]=a0.x+b0.x; y1[1]=a0.y+b0.y; y1[2]=a1.x+b1v.x; y1[3]=a1.y+b1v.y;
        float2 a2 = unpack2(accA[2]), b2v = unpack2(accB[2]);
        float2 a3 = unpack2(accA[3]), b3 = unpack2(accB[3]);
        y2[0]=a2.x+b2v.x; y2[1]=a2.y+b2v.y; y2[2]=a3.x+b3.x; y2[3]=a3.y+b3.y;
    }
    #pragma unroll
    for (int j = 0; j < 4; ++j) {
        int oo = o0 + j;
        float g = dfh_tanh(y1[j] + __ldg(b1+oo)) * dfh_sig(y2[j] + __ldg(b2+oo));
        g_G[(h*8+oo)*GS + w] = g;
    }
}

// ---------------- wave layer: z conv (8ch -> 8 of 16 outs/block) ----------------
__global__ __launch_bounds__(256) void k_convz(
    const float* __restrict__ wzg, const float* __restrict__ bz,
    int H, int W, int XS, int GS)
{
    __shared__ float4 sW[640];
    int half = blockIdx.x & 1;
    int pb   = blockIdx.x >> 1;
    int o0 = half * 8;
    for (int i = threadIdx.x; i < 640; i += 256) {
        int tap = i >> 4, ci = (i >> 1) & 7, part = i & 1;
        sW[i] = *(const float4*)(wzg + tap*128 + ci*16 + o0 + part*4);
    }
    __syncthreads();
    int lane = threadIdx.x & 31, warp = threadIdx.x >> 5;
    int chunks = W >> 5;
    int r = warp / chunks, q = warp - r*chunks;
    int w = (q << 5) + lane;
    int h = pb * (8 / chunks) + r;

    uint64_t accA[4] = {0,0,0,0};
    uint64_t accB[4] = {0,0,0,0};

    for (int kh = 0; kh < 5; ++kh) {
        int hh = h + kh - 2;
        if ((unsigned)hh >= (unsigned)H) continue;
        const float* grow = g_G + hh*8*GS + w;
        #pragma unroll
        for (int kw = 0; kw < 8; ++kw) {
            const float* xp = grow + kw;
            const ulonglong2* wp = (const ulonglong2*)(sW + (kh*8+kw)*16);
            #pragma unroll
            for (int ci = 0; ci < 4; ++ci) {
                uint64_t xv2 = pack2(__ldg(xp + ci*GS));
                ulonglong2 w01 = wp[2*ci];
                ulonglong2 w23 = wp[2*ci+1];
                fma2(accA[0], xv2, w01.x); fma2(accA[1], xv2, w01.y);
                fma2(accA[2], xv2, w23.x); fma2(accA[3], xv2, w23.y);
            }
            #pragma unroll
            for (int ci = 4; ci < 8; ++ci) {
                uint64_t xv2 = pack2(__ldg(xp + ci*GS));
                ulonglong2 w01 = wp[2*ci];
                ulonglong2 w23 = wp[2*ci+1];
                fma2(accB[0], xv2, w01.x); fma2(accB[1], xv2, w01.y);
                fma2(accB[2], xv2, w23.x); fma2(accB[3], xv2, w23.y);
            }
        }
    }
    #pragma unroll
    for (int p = 0; p < 4; ++p) {
        float2 va = unpack2(accA[p]);
        float2 vb = unpack2(accB[p]);
        int oo = o0 + 2*p;
        float z0 = va.x + vb.x + __ldg(bz+oo);
        float z1 = va.y + vb.y + __ldg(bz+oo+1);
        int idx0 = (h*16+oo)*XS + w;
        int idx1 = idx0 + XS;
        g_SKIP[idx0] += z0;  g_X[idx0] += z0;
        g_SKIP[idx1] += z1;  g_X[idx1] += z1;
    }
}

// ---------------- stage C1 ----------------
__global__ void k_c1()
{
    int t = blockIdx.x, f = blockIdx.y;     // 256 x 16
    __shared__ float vr[64], vi[64], tc[128], ts[128];
    int tid = threadIdx.x;                  // 128
    if (tid < 64) {
        int k = tid;
        float cr = g_SKIP[(t*16+f)*160 + 2*k];
        float ci = g_SKIP[(t*16+f)*160 + 2*k+1];
        cr = dfh_tanh(cr); ci = dfh_tanh(ci);
        float s = ((k==0)?0.5f:1.0f) * ((k&1)?-1.0f:1.0f);
        vr[k] = s*cr; vi[k] = s*ci;
    }
    {
        float sv, cv; sincospif((float)tid * (1.0f/64.0f), &sv, &cv);
        tc[tid] = cv; ts[tid] = sv;
    }
    __syncthreads();
    int m = tid;
    float acc = 0.0f;
    #pragma unroll 8
    for (int k = 0; k < 64; ++k) {
        int j = (k*m) & 127;
        acc += vr[k]*tc[j] + vi[k]*ts[j];
    }
    g_R2[(f*128+m)*NTc + t] = acc;
}

// ---------------- stage C2 ----------------
__global__ void k_c2(const float* __restrict__ times)
{
    int m = blockIdx.x, f = blockIdx.y;     // 128 x 16
    __shared__ float v[256], tc[256], ts[256];
    int tid = threadIdx.x;                  // 128
    v[tid]       = g_R2[(f*128+m)*NTc + tid];
    v[tid+128]   = g_R2[(f*128+m)*NTc + tid + 128];
    {
        float sv, cv;
        sincospif((float)tid * (1.0f/128.0f), &sv, &cv);        tc[tid] = cv;      ts[tid] = sv;
        sincospif((float)(tid+128) * (1.0f/128.0f), &sv, &cv);  tc[tid+128] = cv;  ts[tid+128] = sv;
    }
    __syncthreads();
    int k = tid;
    float zm = (k==0) ? 1.0f : ((fabsf(times[2*k]) > 0.0f) ? 1.0f : 0.0f);
    float scale = zm * ((k&1)?-1.0f:1.0f) * (1.0f/128.0f);
    float ar = 0.0f, ai = 0.0f;
    #pragma unroll 8
    for (int t = 0; t < 256; ++t) {
        int j = (t*k) & 255;
        ar += v[t]*tc[j];
        ai += v[t]*ts[j];
    }
    g_HINP[(m*16+f)*NTc + 2*k]   = scale*ar;
    g_HINP[(m*16+f)*NTc + 2*k+1] = scale*ai;
}

// ---------------- dense2 (16->16) ----------------
__global__ void k_dense2(const float* __restrict__ hw, const float* __restrict__ hb)
{
    int c = blockIdx.x;       // 128
    int t = threadIdx.x;      // 256
    float in[16];
    #pragma unroll
    for (int f = 0; f < 16; ++f) in[f] = g_HINP[(c*16+f)*NTc + t];
    #pragma unroll
    for (int o = 0; o < 16; ++o) {
        float acc = hb[o];
        #pragma unroll
        for (int f = 0; f < 16; ++f) acc += in[f]*hw[f*16+o];
        g_X[(c*16+o)*288 + t] = dfh_tanh(acc);
    }
}

// ---------------- stage D ----------------
__global__ void k_stageD()
{
    int c = blockIdx.x, g = blockIdx.y;     // 128 x 32
    __shared__ float hr[128], hi[128], tc[256], ts[256];
    int tid = threadIdx.x;                  // 256
    if (tid < 128) {
        int j = tid;
        float v0, v1;
        if (g < 16) {
            float a = g_SKIP[(c*16+g)*288 + 2*j];   v0 = dfh_tanh(a);
            float b = g_SKIP[(c*16+g)*288 + 2*j+1]; v1 = dfh_tanh(b);
        } else {
            v0 = g_HINP[(c*16+(g-16))*NTc + 2*j];
            v1 = g_HINP[(c*16+(g-16))*NTc + 2*j+1];
        }
        float s = ((j==0)?0.5f:1.0f) * ((j&1)?-1.0f:1.0f);
        hr[j] = s*v0; hi[j] = s*v1;
    }
    {
        float sv, cv; sincospif((float)tid * (1.0f/128.0f), &sv, &cv);
        tc[tid] = cv; ts[tid] = sv;
    }
    __syncthreads();
    int u = tid;
    float acc = 0.0f;
    #pragma unroll 8
    for (int j = 0; j < 128; ++j) {
        int idx = (j*u) & 255;
        acc += hr[j]*tc[idx] + hi[j]*ts[idx];
    }
    g_HFT[(g*128+c)*NTc + u] = acc;
}

// ---------------- fnorm ----------------
__global__ void k_fninit(){ g_FN = 0u; }

__global__ void k_fnred()
{
    int stride = gridDim.x*blockDim.x;
    float mx = 0.0f;
    for (int i = blockIdx.x*blockDim.x + threadIdx.x; i < 1048576; i += stride)
        mx = fmaxf(mx, fabsf(g_HFT[i]));
    #pragma unroll
    for (int o = 16; o; o >>= 1) mx = fmaxf(mx, __shfl_xor_sync(0xFFFFFFFFu, mx, o));
    __shared__ float sm[8];
    int lane = threadIdx.x & 31, warp = threadIdx.x >> 5;
    if (lane == 0) sm[warp] = mx;
    __syncthreads();
    if (warp == 0) {
        mx = (lane < 8) ? sm[lane] : 0.0f;
        #pragma unroll
        for (int o = 4; o; o >>= 1) mx = fmaxf(mx, __shfl_xor_sync(0xFFFFFFFFu, mx, o));
        if (lane == 0) atomicMax(&g_FN, __float_as_uint(mx));
    }
}

__global__ void k_refinit()
{
    float inv = 1.0f/__uint_as_float(g_FN);
    int c = blockIdx.x;     // 128
    int u = threadIdx.x;    // 256
    #pragma unroll 4
    for (int ch = 0; ch < 64; ++ch)
        g_RA[ch*RCH + c*RSTR + 4 + u] = g_HFT[(ch & 31)*32768 + c*256 + u] * inv;
}

// ---------------- FUSED refine conv: tt (tanh) + rr (relu) in one pass ----------------
// grid = 512: c = bid>>2, osel = bid&3 -> outputs o0..o0+7 of EACH conv
// Per (kw,ci): 16 smem floats = [tt o0..o0+7 | rr o0..o0+7]
__global__ __launch_bounds__(256) void k_refconv(
    const float* __restrict__ Wt, const float* __restrict__ Wr,
    const float* __restrict__ Bt, const float* __restrict__ Br,
    int swap)
{
    const float* RIN  = swap ? g_RB : g_RA;
    float*       ROUT = swap ? g_RA : g_RB;
    int c    = blockIdx.x >> 2;
    int osel = blockIdx.x & 3;
    int o0   = osel * 8;
    int u    = threadIdx.x;       // 256
    __shared__ float4 sw[2304];   // per-kh stage: [kw(9)][ci(64)][4 float4] = 36KB

    uint64_t accT[4] = {0,0,0,0};
    uint64_t accR[4] = {0,0,0,0};

    for (int kh = 0; kh < 9; ++kh) {
        __syncthreads();
        for (int i = threadIdx.x; i < 2304; i += 256) {
            int kwci = i >> 2, part = i & 3;
            int koff = (kh*9 + (kwci >> 6))*2048 + (kwci & 63)*32 + o0;
            const float* src = (part < 2) ? (Wt + koff + part*4)
                                          : (Wr + koff + (part-2)*4);
            sw[i] = *(const float4*)src;
        }
        __syncthreads();

        int cc = c + kh - 4;
        if ((unsigned)cc >= 128u) continue;      // block-uniform
        const float* rowp = RIN + cc*RSTR + u;   // +4 pad merged with kw-4
        for (int kw = 0; kw < 9; ++kw) {
            const float* xp = rowp + kw;
            const ulonglong2* wp = (const ulonglong2*)(sw + kw*256);
            #pragma unroll 8
            for (int ci = 0; ci < 64; ++ci) {
                uint64_t xv2 = pack2(__ldg(xp + ci*RCH));
                ulonglong2 t01 = wp[4*ci];
                ulonglong2 t23 = wp[4*ci+1];
                ulonglong2 r01 = wp[4*ci+2];
                ulonglong2 r23 = wp[4*ci+3];
                fma2(accT[0], xv2, t01.x); fma2(accT[1], xv2, t01.y);
                fma2(accT[2], xv2, t23.x); fma2(accT[3], xv2, t23.y);
                fma2(accR[0], xv2, r01.x); fma2(accR[1], xv2, r01.y);
                fma2(accR[2], xv2, r23.x); fma2(accR[3], xv2, r23.y);
            }
        }
    }
    int pos = c*RSTR + 4 + u;
    #pragma unroll
    for (int p = 0; p < 4; ++p) {
        float2 vt = unpack2(accT[p]);
        float2 vr = unpack2(accR[p]);
        float tv[2] = {vt.x, vt.y};
        float rv[2] = {vr.x, vr.y};
        #pragma unroll
        for (int s = 0; s < 2; ++s) {
            int k = o0 + 2*p + s;
            float t = dfh_tanh(tv[s] + __ldg(Bt + k));
            float rraw = rv[s] + __ldg(Br + k);
            float r = (rraw > 0.0f ? rraw : 0.0f)*0.98f + 0.02f*rraw;
            ROUT[k*RCH + pos]      = t + RIN[k*RCH + pos];        // tt -> ch 0..31
            ROUT[(32+k)*RCH + pos] = r + RIN[(32+k)*RCH + pos];   // rr -> ch 32..63
        }
    }
}

// ---------------- final dense (96 -> 2) ----------------
__global__ void k_final(const float* __restrict__ dw, const float* __restrict__ db,
                        float* __restrict__ out)
{
    int c = blockIdx.x;     // 128
    int u = threadIdx.x;    // 256
    int rpos = c*RSTR + 4 + u;
    int hpos = c*256 + u;
    float fn = __uint_as_float(g_FN);
    float a0 = __ldg(db), a1 = __ldg(db+1);
    #pragma unroll 8
    for (int p = 0; p < 64; ++p) {
        float v = g_RA[p*RCH + rpos] * fn;
        a0 += v*__ldg(dw + 2*p);
        a1 += v*__ldg(dw + 2*p + 1);
    }
    #pragma unroll 8
    for (int q = 0; q < 32; ++q) {
        float v = g_HFT[q*32768 + hpos];
        a0 += v*__ldg(dw + 2*(64+q));
        a1 += v*__ldg(dw + 2*(64+q) + 1);
    }
    out[hpos*2]     = a0;
    out[hpos*2 + 1] = a1/fn;
}

// ---------------- launch ----------------
extern "C" void kernel_launch(void* const* d_in, const int* in_sizes, int n_in,
                              void* d_out, int out_size)
{
    const float* times    = (const float*)d_in[0];
    const float* times_in = (const float*)d_in[1];
    const float* inp_nc   = (const float*)d_in[2];
    const float* inp_c    = (const float*)d_in[3];
    const float* cdw  = (const float*)d_in[4];
    const float* cdb  = (const float*)d_in[5];
    const float* cwy1 = (const float*)d_in[6];
    const float* cby1 = (const float*)d_in[7];
    const float* cwy2 = (const float*)d_in[8];
    const float* cby2 = (const float*)d_in[9];
    const float* cwz0 = (const float*)d_in[10];
    const float* cbz0 = (const float*)d_in[11];
    const float* hdw  = (const float*)d_in[12];
    const float* hdb  = (const float*)d_in[13];
    const float* hwy1 = (const float*)d_in[14];
    const float* hby1 = (const float*)d_in[15];
    const float* hwy2 = (const float*)d_in[16];
    const float* hby2 = (const float*)d_in[17];
    const float* hwz0 = (const float*)d_in[18];
    const float* hbz0 = (const float*)d_in[19];
    const float* rwr  = (const float*)d_in[20];
    const float* rbr  = (const float*)d_in[21];
    const float* rwt  = (const float*)d_in[22];
    const float* rbt  = (const float*)d_in[23];
    const float* dw   = (const float*)d_in[24];
    const float* db   = (const float*)d_in[25];
    float* out = (float*)d_out;

    static const int DILS[15] = {1,2,3,4,6,8,10,12,14,16,18,20,24,28,32};

    // ---- fidnet 1: H=256, W=128, XS=160, GS=136 ----
    k_zero3<<<512,256>>>();
    k_dense1<<<256,128>>>(inp_nc, inp_c, times, times_in, cdw, cdb);
    for (int i = 0; i < 45; ++i) {
        int d = DILS[i % 15];
        k_conv12<<<256,256>>>(cwy1 + i*5120, cby1 + i*8, cwy2 + i*5120, cby2 + i*8,
                              256, 128, 160, 136, d);
        k_convz <<<256,256>>>(cwz0 + i*5120, cbz0 + i*16, 256, 128, 160, 136);
    }

    // ---- spectral glue ----
    k_c1<<<dim3(256,16),128>>>();
    k_c2<<<dim3(128,16),128>>>(times);

    // ---- fidnet 2: H=128, W=256, XS=288, GS=264 ----
    k_zero3<<<512,256>>>();
    k_dense2<<<128,256>>>(hdw, hdb);
    for (int i = 0; i < 45; ++i) {
        int d = DILS[i % 15];
        k_conv12<<<256,256>>>(hwy1 + i*5120, hby1 + i*8, hwy2 + i*5120, hby2 + i*8,
                              128, 256, 288, 264, d);
        k_convz <<<256,256>>>(hwz0 + i*5120, hbz0 + i*16, 128, 256, 288, 264);
    }

    // ---- hout_ft ----
    k_stageD<<<dim3(128,32),256>>>();

    // ---- fnorm + refine ----
    k_fninit<<<1,1>>>();
    k_fnred<<<256,256>>>();
    k_zeroref<<<512,256>>>();
    k_refinit<<<128,256>>>();
    for (int i = 0; i < 4; ++i) {
        k_refconv<<<512,256>>>(rwt + i*165888, rwr + i*165888,
                               rbt + i*32, rbr + i*32, i & 1);
    }

    // ---- final dense + output ----
    k_final<<<128,256>>>(dw, db, out);
}

// round 8
// speedup vs baseline: 1.6683x; 1.0582x over previous
#include <cuda_runtime.h>
#include <math.h>
#include <stdint.h>

// ---------------- constants ----------------
#define NCc 128
#define NTc 256
#define RSTR 264          // refine padded row stride (4 zero guards each side)
#define RCH  33792        // 128*264 per refine channel

__device__ __constant__ int c_DILS[15] = {1,2,3,4,6,8,10,12,14,16,18,20,24,28,32};

// ---------------- scratch ----------------
__device__ float g_X[655360];     // activations [H][16][XS] (padded)
__device__ float g_SKIP[655360];  // skip accumulator
__device__ float g_G[278528];     // gated intermediate [H][8][GS] (padded)
__device__ float g_R2[524288];    // [f(16)][m(128)][t(256)]
__device__ float g_HINP[524288];  // [c(128)][f(16)][t(256)]
__device__ float g_HFT[1048576];  // [g(32)][c(128)][u(256)]
__device__ float g_RA[2162688];   // refine ping [ch(64)][c(128)][RSTR]
__device__ float g_RB[2162688];   // refine pong
__device__ unsigned g_FN;
__device__ unsigned g_barcnt;     // persistent-kernel grid barrier counter

__device__ __forceinline__ float dfh_tanh(float x){ return tanhf(x)*0.98f + 0.02f*x; }
__device__ __forceinline__ float dfh_sig (float x){ return 0.98f/(1.0f+expf(-x)) + 0.02f*x; }

// ---------------- packed f32x2 helpers ----------------
__device__ __forceinline__ void fma2(uint64_t &d, uint64_t a, uint64_t b){
    asm("fma.rn.f32x2 %0, %1, %2, %0;" : "+l"(d) : "l"(a), "l"(b));
}
__device__ __forceinline__ uint64_t pack2(float x){
    uint64_t r; asm("mov.b64 %0, {%1, %1};" : "=l"(r) : "f"(x)); return r;
}
__device__ __forceinline__ float2 unpack2(uint64_t v){
    float2 f; asm("mov.b64 {%0, %1}, %2;" : "=f"(f.x), "=f"(f.y) : "l"(v)); return f;
}

// ---------------- grid barrier (all 256 blocks resident by __launch_bounds__(256,2)) ----------------
__device__ __forceinline__ void gridbar(unsigned &target)
{
    __syncthreads();
    target += 256u;
    if (threadIdx.x == 0) {
        __threadfence();                      // release my writes
        atomicAdd(&g_barcnt, 1u);
        while (*((volatile unsigned*)&g_barcnt) < target) { }
        __threadfence();                      // acquire others' writes
    }
    __syncthreads();
}

// ---------------- zero helpers ----------------
__global__ void k_zero3()
{
    if (blockIdx.x == 0 && threadIdx.x == 0) g_barcnt = 0u;
    int stride = gridDim.x*blockDim.x;
    for (int i = blockIdx.x*blockDim.x + threadIdx.x; i < 655360; i += stride) {
        g_X[i] = 0.0f; g_SKIP[i] = 0.0f;
        if (i < 278528) g_G[i] = 0.0f;
    }
}
__global__ void k_zeroref()
{
    int stride = gridDim.x*blockDim.x;
    for (int i = blockIdx.x*blockDim.x + threadIdx.x; i < 2162688; i += stride) {
        g_RA[i] = 0.0f; g_RB[i] = 0.0f;
    }
}

// ---------------- input dense (4->16) ----------------
__global__ void k_dense1(const float* __restrict__ inc, const float* __restrict__ icc,
                         const float* __restrict__ times, const float* __restrict__ tin,
                         const float* __restrict__ cw, const float* __restrict__ cb)
{
    int t = blockIdx.x, c = threadIdx.x;  // 256 x 128
    float i0 = inc[c*NTc + t];
    float i1 = icc[c*NTc + t];
    float i2 = times[t];
    float i3 = tin[c];
    #pragma unroll
    for (int o = 0; o < 16; ++o) {
        float v = i0*cw[o] + i1*cw[16+o] + i2*cw[32+o] + i3*cw[48+o] + cb[o];
        g_X[(t*16+o)*160 + c] = dfh_tanh(v);
    }
}

// ---------------- PERSISTENT wave stack: all 45 layers, both phases ----------------
// grid MUST be 256 blocks x 256 threads; 2 blocks/SM guaranteed by launch bounds.
// Activation accesses use plain loads (memory-model-coherent across gridbar);
// weights/biases are truly read-only -> __ldg OK.
__global__ __launch_bounds__(256,2) void k_wave_all(
    const float* __restrict__ wy1a, const float* __restrict__ by1a,
    const float* __restrict__ wy2a, const float* __restrict__ by2a,
    const float* __restrict__ wza,  const float* __restrict__ bza,
    int H, int W, int XS, int GS)
{
    __shared__ float4 sW[1280];   // 20KB: conv12 uses all, convz uses first 640
    int tidx = threadIdx.x;
    int lane = tidx & 31, warp = tidx >> 5;
    int chunks = W >> 5;                  // 4 (W=128) or 8 (W=256)
    int r = warp / chunks, q = warp - r*chunks;
    int w = (q << 5) + lane;
    int half = blockIdx.x & 1;
    int pb   = blockIdx.x >> 1;
    int h = pb * (8 / chunks) + r;
    unsigned target = 0;

    for (int layer = 0; layer < 45; ++layer) {
        int dil = c_DILS[layer % 15];

        // ======== phase 1: gated conv pair (16ch -> 4+4 outs) ========
        {
            const float* w1g = wy1a + layer*5120;
            const float* w2g = wy2a + layer*5120;
            const float* b1  = by1a + layer*8;
            const float* b2  = by2a + layer*8;
            int o0 = half*4;
            for (int i = tidx; i < 1280; i += 256) {
                int tap = i >> 5, ci = (i >> 1) & 15, which = i & 1;
                const float* src = (which ? w2g : w1g) + tap*128 + ci*8 + o0;
                sW[i] = *(const float4*)src;
            }
            __syncthreads();

            uint64_t accA[4] = {0,0,0,0};   // ci 0..7
            uint64_t accB[4] = {0,0,0,0};   // ci 8..15

            for (int kh = 0; kh < 5; ++kh) {
                int hh = h + kh - 2;
                if ((unsigned)hh >= (unsigned)H) continue;
                const float* xrow = g_X + hh*16*XS;
                for (int kw = 0; kw < 8; ++kw) {
                    int cb0 = (q << 5) + kw*dil;
                    if (cb0 >= W) break;               // warp-uniform
                    const float* xp = xrow + cb0 + lane;
                    const ulonglong2* wp = (const ulonglong2*)(sW + (kh*8+kw)*32);
                    #pragma unroll
                    for (int ci = 0; ci < 8; ++ci) {
                        uint64_t xv2 = pack2(xp[ci*XS]);        // plain load (coherent)
                        ulonglong2 wv1 = wp[2*ci];
                        ulonglong2 wv2 = wp[2*ci+1];
                        fma2(accA[0], xv2, wv1.x); fma2(accA[1], xv2, wv1.y);
                        fma2(accA[2], xv2, wv2.x); fma2(accA[3], xv2, wv2.y);
                    }
                    #pragma unroll
                    for (int ci = 8; ci < 16; ++ci) {
                        uint64_t xv2 = pack2(xp[ci*XS]);
                        ulonglong2 wv1 = wp[2*ci];
                        ulonglong2 wv2 = wp[2*ci+1];
                        fma2(accB[0], xv2, wv1.x); fma2(accB[1], xv2, wv1.y);
                        fma2(accB[2], xv2, wv2.x); fma2(accB[3], xv2, wv2.y);
                    }
                }
            }
            float y1[4], y2[4];
            {
                float2 a0 = unpack2(accA[0]), b0 = unpack2(accB[0]);
                float2 a1 = unpack2(accA[1]), b1v = unpack2(accB[1]);
                y1[0]=a0.x+b0.x; y1[1]=a0.y+b0.y; y1[2]=a1.x+b1v.x; y1[3]=a1.y+b1v.y;
                float2 a2 = unpack2(accA[2]), b2v = unpack2(accB[2]);
                float2 a3 = unpack2(accA[3]), b3 = unpack2(accB[3]);
                y2[0]=a2.x+b2v.x; y2[1]=a2.y+b2v.y; y2[2]=a3.x+b3.x; y2[3]=a3.y+b3.y;
            }
            #pragma unroll
            for (int j = 0; j < 4; ++j) {
                int oo = o0 + j;
                float g = dfh_tanh(y1[j] + __ldg(b1+oo)) * dfh_sig(y2[j] + __ldg(b2+oo));
                g_G[(h*8+oo)*GS + w] = g;
            }
        }
        gridbar(target);

        // ======== phase 2: z conv (8ch -> 8 of 16 outs) ========
        {
            const float* wzg = wza + layer*5120;
            const float* bz  = bza + layer*16;
            int o0 = half * 8;
            for (int i = tidx; i < 640; i += 256) {
                int tap = i >> 4, ci = (i >> 1) & 7, part = i & 1;
                sW[i] = *(const float4*)(wzg + tap*128 + ci*16 + o0 + part*4);
            }
            __syncthreads();

            uint64_t accA[4] = {0,0,0,0};
            uint64_t accB[4] = {0,0,0,0};

            for (int kh = 0; kh < 5; ++kh) {
                int hh = h + kh - 2;
                if ((unsigned)hh >= (unsigned)H) continue;
                const float* grow = g_G + hh*8*GS + w;
                #pragma unroll
                for (int kw = 0; kw < 8; ++kw) {
                    const float* xp = grow + kw;              // zero pad: no guard
                    const ulonglong2* wp = (const ulonglong2*)(sW + (kh*8+kw)*16);
                    #pragma unroll
                    for (int ci = 0; ci < 4; ++ci) {
                        uint64_t xv2 = pack2(xp[ci*GS]);      // plain load
                        ulonglong2 w01 = wp[2*ci];
                        ulonglong2 w23 = wp[2*ci+1];
                        fma2(accA[0], xv2, w01.x); fma2(accA[1], xv2, w01.y);
                        fma2(accA[2], xv2, w23.x); fma2(accA[3], xv2, w23.y);
                    }
                    #pragma unroll
                    for (int ci = 4; ci < 8; ++ci) {
                        uint64_t xv2 = pack2(xp[ci*GS]);
                        ulonglong2 w01 = wp[2*ci];
                        ulonglong2 w23 = wp[2*ci+1];
                        fma2(accB[0], xv2, w01.x); fma2(accB[1], xv2, w01.y);
                        fma2(accB[2], xv2, w23.x); fma2(accB[3], xv2, w23.y);
                    }
                }
            }
            #pragma unroll
            for (int p = 0; p < 4; ++p) {
                float2 va = unpack2(accA[p]);
                float2 vb = unpack2(accB[p]);
                int oo = o0 + 2*p;
                float z0 = va.x + vb.x + __ldg(bz+oo);
                float z1 = va.y + vb.y + __ldg(bz+oo+1);
                int idx0 = (h*16+oo)*XS + w;
                int idx1 = idx0 + XS;
                g_SKIP[idx0] += z0;  g_X[idx0] += z0;
                g_SKIP[idx1] += z1;  g_X[idx1] += z1;
            }
        }
        gridbar(target);
    }
}

// ---------------- stage C1 ----------------
__global__ void k_c1()
{
    int t = blockIdx.x, f = blockIdx.y;     // 256 x 16
    __shared__ float vr[64], vi[64], tc[128], ts[128];
    int tid = threadIdx.x;                  // 128
    if (tid < 64) {
        int k = tid;
        float cr = g_SKIP[(t*16+f)*160 + 2*k];
        float ci = g_SKIP[(t*16+f)*160 + 2*k+1];
        cr = dfh_tanh(cr); ci = dfh_tanh(ci);
        float s = ((k==0)?0.5f:1.0f) * ((k&1)?-1.0f:1.0f);
        vr[k] = s*cr; vi[k] = s*ci;
    }
    {
        float sv, cv; sincospif((float)tid * (1.0f/64.0f), &sv, &cv);
        tc[tid] = cv; ts[tid] = sv;
    }
    __syncthreads();
    int m = tid;
    float acc = 0.0f;
    #pragma unroll 8
    for (int k = 0; k < 64; ++k) {
        int j = (k*m) & 127;
        acc += vr[k]*tc[j] + vi[k]*ts[j];
    }
    g_R2[(f*128+m)*NTc + t] = acc;
}

// ---------------- stage C2 ----------------
__global__ void k_c2(const float* __restrict__ times)
{
    int m = blockIdx.x, f = blockIdx.y;     // 128 x 16
    __shared__ float v[256], tc[256], ts[256];
    int tid = threadIdx.x;                  // 128
    v[tid]       = g_R2[(f*128+m)*NTc + tid];
    v[tid+128]   = g_R2[(f*128+m)*NTc + tid + 128];
    {
        float sv, cv;
        sincospif((float)tid * (1.0f/128.0f), &sv, &cv);        tc[tid] = cv;      ts[tid] = sv;
        sincospif((float)(tid+128) * (1.0f/128.0f), &sv, &cv);  tc[tid+128] = cv;  ts[tid+128] = sv;
    }
    __syncthreads();
    int k = tid;
    float zm = (k==0) ? 1.0f : ((fabsf(times[2*k]) > 0.0f) ? 1.0f : 0.0f);
    float scale = zm * ((k&1)?-1.0f:1.0f) * (1.0f/128.0f);
    float ar = 0.0f, ai = 0.0f;
    #pragma unroll 8
    for (int t = 0; t < 256; ++t) {
        int j = (t*k) & 255;
        ar += v[t]*tc[j];
        ai += v[t]*ts[j];
    }
    g_HINP[(m*16+f)*NTc + 2*k]   = scale*ar;
    g_HINP[(m*16+f)*NTc + 2*k+1] = scale*ai;
}

// ---------------- dense2 (16->16) ----------------
__global__ void k_dense2(const float* __restrict__ hw, const float* __restrict__ hb)
{
    int c = blockIdx.x;       // 128
    int t = threadIdx.x;      // 256
    float in[16];
    #pragma unroll
    for (int f = 0; f < 16; ++f) in[f] = g_HINP[(c*16+f)*NTc + t];
    #pragma unroll
    for (int o = 0; o < 16; ++o) {
        float acc = hb[o];
        #pragma unroll
        for (int f = 0; f < 16; ++f) acc += in[f]*hw[f*16+o];
        g_X[(c*16+o)*288 + t] = dfh_tanh(acc);
    }
}

// ---------------- stage D ----------------
__global__ void k_stageD()
{
    int c = blockIdx.x, g = blockIdx.y;     // 128 x 32
    __shared__ float hr[128], hi[128], tc[256], ts[256];
    int tid = threadIdx.x;                  // 256
    if (tid < 128) {
        int j = tid;
        float v0, v1;
        if (g < 16) {
            float a = g_SKIP[(c*16+g)*288 + 2*j];   v0 = dfh_tanh(a);
            float b = g_SKIP[(c*16+g)*288 + 2*j+1]; v1 = dfh_tanh(b);
        } else {
            v0 = g_HINP[(c*16+(g-16))*NTc + 2*j];
            v1 = g_HINP[(c*16+(g-16))*NTc + 2*j+1];
        }
        float s = ((j==0)?0.5f:1.0f) * ((j&1)?-1.0f:1.0f);
        hr[j] = s*v0; hi[j] = s*v1;
    }
    {
        float sv, cv; sincospif((float)tid * (1.0f/128.0f), &sv, &cv);
        tc[tid] = cv; ts[tid] = sv;
    }
    __syncthreads();
    int u = tid;
    float acc = 0.0f;
    #pragma unroll 8
    for (int j = 0; j < 128; ++j) {
        int idx = (j*u) & 255;
        acc += hr[j]*tc[idx] + hi[j]*ts[idx];
    }
    g_HFT[(g*128+c)*NTc + u] = acc;
}

// ---------------- fnorm ----------------
__global__ void k_fninit(){ g_FN = 0u; }

__global__ void k_fnred()
{
    int stride = gridDim.x*blockDim.x;
    float mx = 0.0f;
    for (int i = blockIdx.x*blockDim.x + threadIdx.x; i < 1048576; i += stride)
        mx = fmaxf(mx, fabsf(g_HFT[i]));
    #pragma unroll
    for (int o = 16; o; o >>= 1) mx = fmaxf(mx, __shfl_xor_sync(0xFFFFFFFFu, mx, o));
    __shared__ float sm[8];
    int lane = threadIdx.x & 31, warp = threadIdx.x >> 5;
    if (lane == 0) sm[warp] = mx;
    __syncthreads();
    if (warp == 0) {
        mx = (lane < 8) ? sm[lane] : 0.0f;
        #pragma unroll
        for (int o = 4; o; o >>= 1) mx = fmaxf(mx, __shfl_xor_sync(0xFFFFFFFFu, mx, o));
        if (lane == 0) atomicMax(&g_FN, __float_as_uint(mx));
    }
}

__global__ void k_refinit()
{
    float inv = 1.0f/__uint_as_float(g_FN);
    int c = blockIdx.x;     // 128
    int u = threadIdx.x;    // 256
    #pragma unroll 4
    for (int ch = 0; ch < 64; ++ch)
        g_RA[ch*RCH + c*RSTR + 4 + u] = g_HFT[(ch & 31)*32768 + c*256 + u] * inv;
}

// ---------------- FUSED refine conv: tt (tanh) + rr (relu) in one pass ----------------
__global__ __launch_bounds__(256) void k_refconv(
    const float* __restrict__ Wt, const float* __restrict__ Wr,
    const float* __restrict__ Bt, const float* __restrict__ Br,
    int swap)
{
    const float* RIN  = swap ? g_RB : g_RA;
    float*       ROUT = swap ? g_RA : g_RB;
    int c    = blockIdx.x >> 2;
    int osel = blockIdx.x & 3;
    int o0   = osel * 8;
    int u    = threadIdx.x;       // 256
    __shared__ float4 sw[2304];   // per-kh stage: [kw(9)][ci(64)][4 float4] = 36KB

    uint64_t accT[4] = {0,0,0,0};
    uint64_t accR[4] = {0,0,0,0};

    for (int kh = 0; kh < 9; ++kh) {
        __syncthreads();
        for (int i = threadIdx.x; i < 2304; i += 256) {
            int kwci = i >> 2, part = i & 3;
            int koff = (kh*9 + (kwci >> 6))*2048 + (kwci & 63)*32 + o0;
            const float* src = (part < 2) ? (Wt + koff + part*4)
                                          : (Wr + koff + (part-2)*4);
            sw[i] = *(const float4*)src;
        }
        __syncthreads();

        int cc = c + kh - 4;
        if ((unsigned)cc >= 128u) continue;      // block-uniform
        const float* rowp = RIN + cc*RSTR + u;
        for (int kw = 0; kw < 9; ++kw) {
            const float* xp = rowp + kw;
            const ulonglong2* wp = (const ulonglong2*)(sw + kw*256);
            #pragma unroll 8
            for (int ci = 0; ci < 64; ++ci) {
                uint64_t xv2 = pack2(__ldg(xp + ci*RCH));
                ulonglong2 t01 = wp[4*ci];
                ulonglong2 t23 = wp[4*ci+1];
                ulonglong2 r01 = wp[4*ci+2];
                ulonglong2 r23 = wp[4*ci+3];
                fma2(accT[0], xv2, t01.x); fma2(accT[1], xv2, t01.y);
                fma2(accT[2], xv2, t23.x); fma2(accT[3], xv2, t23.y);
                fma2(accR[0], xv2, r01.x); fma2(accR[1], xv2, r01.y);
                fma2(accR[2], xv2, r23.x); fma2(accR[3], xv2, r23.y);
            }
        }
    }
    int pos = c*RSTR + 4 + u;
    #pragma unroll
    for (int p = 0; p < 4; ++p) {
        float2 vt = unpack2(accT[p]);
        float2 vr = unpack2(accR[p]);
        float tv[2] = {vt.x, vt.y};
        float rv[2] = {vr.x, vr.y};
        #pragma unroll
        for (int s = 0; s < 2; ++s) {
            int k = o0 + 2*p + s;
            float t = dfh_tanh(tv[s] + __ldg(Bt + k));
            float rraw = rv[s] + __ldg(Br + k);
            float r = (rraw > 0.0f ? rraw : 0.0f)*0.98f + 0.02f*rraw;
            ROUT[k*RCH + pos]      = t + RIN[k*RCH + pos];
            ROUT[(32+k)*RCH + pos] = r + RIN[(32+k)*RCH + pos];
        }
    }
}

// ---------------- final dense (96 -> 2) ----------------
__global__ void k_final(const float* __restrict__ dw, const float* __restrict__ db,
                        float* __restrict__ out)
{
    int c = blockIdx.x;     // 128
    int u = threadIdx.x;    // 256
    int rpos = c*RSTR + 4 + u;
    int hpos = c*256 + u;
    float fn = __uint_as_float(g_FN);
    float a0 = __ldg(db), a1 = __ldg(db+1);
    #pragma unroll 8
    for (int p = 0; p < 64; ++p) {
        float v = g_RA[p*RCH + rpos] * fn;
        a0 += v*__ldg(dw + 2*p);
        a1 += v*__ldg(dw + 2*p + 1);
    }
    #pragma unroll 8
    for (int q = 0; q < 32; ++q) {
        float v = g_HFT[q*32768 + hpos];
        a0 += v*__ldg(dw + 2*(64+q));
        a1 += v*__ldg(dw + 2*(64+q) + 1);
    }
    out[hpos*2]     = a0;
    out[hpos*2 + 1] = a1/fn;
}

// ---------------- launch ----------------
extern "C" void kernel_launch(void* const* d_in, const int* in_sizes, int n_in,
                              void* d_out, int out_size)
{
    const float* times    = (const float*)d_in[0];
    const float* times_in = (const float*)d_in[1];
    const float* inp_nc   = (const float*)d_in[2];
    const float* inp_c    = (const float*)d_in[3];
    const float* cdw  = (const float*)d_in[4];
    const float* cdb  = (const float*)d_in[5];
    const float* cwy1 = (const float*)d_in[6];
    const float* cby1 = (const float*)d_in[7];
    const float* cwy2 = (const float*)d_in[8];
    const float* cby2 = (const float*)d_in[9];
    const float* cwz0 = (const float*)d_in[10];
    const float* cbz0 = (const float*)d_in[11];
    const float* hdw  = (const float*)d_in[12];
    const float* hdb  = (const float*)d_in[13];
    const float* hwy1 = (const float*)d_in[14];
    const float* hby1 = (const float*)d_in[15];
    const float* hwy2 = (const float*)d_in[16];
    const float* hby2 = (const float*)d_in[17];
    const float* hwz0 = (const float*)d_in[18];
    const float* hbz0 = (const float*)d_in[19];
    const float* rwr  = (const float*)d_in[20];
    const float* rbr  = (const float*)d_in[21];
    const float* rwt  = (const float*)d_in[22];
    const float* rbt  = (const float*)d_in[23];
    const float* dw   = (const float*)d_in[24];
    const float* db   = (const float*)d_in[25];
    float* out = (float*)d_out;

    // ---- fidnet 1: H=256, W=128, XS=160, GS=136 ----
    k_zero3<<<512,256>>>();           // also resets g_barcnt
    k_dense1<<<256,128>>>(inp_nc, inp_c, times, times_in, cdw, cdb);
    k_wave_all<<<256,256>>>(cwy1, cby1, cwy2, cby2, cwz0, cbz0, 256, 128, 160, 136);

    // ---- spectral glue ----
    k_c1<<<dim3(256,16),128>>>();
    k_c2<<<dim3(128,16),128>>>(times);

    // ---- fidnet 2: H=128, W=256, XS=288, GS=264 ----
    k_zero3<<<512,256>>>();           // resets g_barcnt again
    k_dense2<<<128,256>>>(hdw, hdb);
    k_wave_all<<<256,256>>>(hwy1, hby1, hwy2, hby2, hwz0, hbz0, 128, 256, 288, 264);

    // ---- hout_ft ----
    k_stageD<<<dim3(128,32),256>>>();

    // ---- fnorm + refine ----
    k_fninit<<<1,1>>>();
    k_fnred<<<256,256>>>();
    k_zeroref<<<512,256>>>();
    k_refinit<<<128,256>>>();
    for (int i = 0; i < 4; ++i) {
        k_refconv<<<512,256>>>(rwt + i*165888, rwr + i*165888,
                               rbt + i*32, rbr + i*32, i & 1);
    }

    // ---- final dense + output ----
    k_final<<<128,256>>>(dw, db, out);
}

// round 9
// speedup vs baseline: 1.6822x; 1.0083x over previous
#include <cuda_runtime.h>
#include <math.h>
#include <stdint.h>

// ---------------- constants ----------------
#define NCc 128
#define NTc 256
#define RSTR 264          // refine padded row stride (4 zero guards each side)
#define RCH  33792        // 128*264 per refine channel

__device__ __constant__ int c_DILS[15] = {1,2,3,4,6,8,10,12,14,16,18,20,24,28,32};

// ---------------- scratch ----------------
__device__ float g_X[655360];     // activations [H][16][XS] (padded)
__device__ float g_SKIP[655360];  // skip accumulator
__device__ float g_G[278528];     // gated intermediate [H][8][GS] (padded)
__device__ float g_R2[524288];    // [f(16)][m(128)][t(256)]
__device__ float g_HINP[524288];  // [c(128)][f(16)][t(256)]
__device__ float g_HFT[1048576];  // [g(32)][c(128)][u(256)]
__device__ float g_RA[2162688];   // refine ping [ch(64)][c(128)][RSTR]
__device__ float g_RB[2162688];   // refine pong
__device__ unsigned g_FN;
__device__ unsigned g_barcnt;     // persistent-kernel grid barrier counter

__device__ __forceinline__ float dfh_tanh(float x){ return tanhf(x)*0.98f + 0.02f*x; }
__device__ __forceinline__ float dfh_sig (float x){ return 0.98f/(1.0f+expf(-x)) + 0.02f*x; }

// ---------------- packed f32x2 helpers ----------------
__device__ __forceinline__ void fma2(uint64_t &d, uint64_t a, uint64_t b){
    asm("fma.rn.f32x2 %0, %1, %2, %0;" : "+l"(d) : "l"(a), "l"(b));
}
__device__ __forceinline__ uint64_t pack2(float x){
    uint64_t r; asm("mov.b64 %0, {%1, %1};" : "=l"(r) : "f"(x)); return r;
}
__device__ __forceinline__ float2 unpack2(uint64_t v){
    float2 f; asm("mov.b64 {%0, %1}, %2;" : "=f"(f.x), "=f"(f.y) : "l"(v)); return f;
}

// ---------------- grid barrier (256 blocks resident via __launch_bounds__(256,2)) ----------------
__device__ __forceinline__ void gridbar(unsigned &target)
{
    __syncthreads();
    target += 256u;
    if (threadIdx.x == 0) {
        __threadfence();
        atomicAdd(&g_barcnt, 1u);
        while (*((volatile unsigned*)&g_barcnt) < target) { }
        __threadfence();
    }
    __syncthreads();
}

// ---------------- zero helpers ----------------
__global__ void k_zero3()
{
    if (blockIdx.x == 0 && threadIdx.x == 0) g_barcnt = 0u;
    int stride = gridDim.x*blockDim.x;
    for (int i = blockIdx.x*blockDim.x + threadIdx.x; i < 655360; i += stride) {
        g_X[i] = 0.0f; g_SKIP[i] = 0.0f;
        if (i < 278528) g_G[i] = 0.0f;
    }
}
__global__ void k_zeroref()
{
    int stride = gridDim.x*blockDim.x;
    for (int i = blockIdx.x*blockDim.x + threadIdx.x; i < 2162688; i += stride) {
        g_RA[i] = 0.0f; g_RB[i] = 0.0f;
    }
}

// ---------------- input dense (4->16) ----------------
__global__ void k_dense1(const float* __restrict__ inc, const float* __restrict__ icc,
                         const float* __restrict__ times, const float* __restrict__ tin,
                         const float* __restrict__ cw, const float* __restrict__ cb)
{
    int t = blockIdx.x, c = threadIdx.x;  // 256 x 128
    float i0 = inc[c*NTc + t];
    float i1 = icc[c*NTc + t];
    float i2 = times[t];
    float i3 = tin[c];
    #pragma unroll
    for (int o = 0; o < 16; ++o) {
        float v = i0*cw[o] + i1*cw[16+o] + i2*cw[32+o] + i3*cw[48+o] + cb[o];
        g_X[(t*16+o)*160 + c] = dfh_tanh(v);
    }
}

// ---------------- PERSISTENT wave stack (templated: compile-time strides) ----------------
template<int H, int W, int XS, int GS>
__global__ __launch_bounds__(256,2) void k_wave_all(
    const float* __restrict__ wy1a, const float* __restrict__ by1a,
    const float* __restrict__ wy2a, const float* __restrict__ by2a,
    const float* __restrict__ wza,  const float* __restrict__ bza)
{
    constexpr int CHUNKS = W >> 5;
    constexpr int RPB    = 8 / CHUNKS;
    __shared__ float4 sW[1280];   // 20KB
    int tidx = threadIdx.x;
    int lane = tidx & 31, warp = tidx >> 5;
    int r = warp / CHUNKS, q = warp - r*CHUNKS;
    int w = (q << 5) + lane;
    int half = blockIdx.x & 1;
    int pb   = blockIdx.x >> 1;
    int h = pb * RPB + r;
    unsigned target = 0;

    for (int layer = 0; layer < 45; ++layer) {
        int dil = c_DILS[layer % 15];

        // ======== phase 1: gated conv pair (16ch -> 4+4 outs) ========
        {
            const float* w1g = wy1a + layer*5120;
            const float* w2g = wy2a + layer*5120;
            const float* b1  = by1a + layer*8;
            const float* b2  = by2a + layer*8;
            int o0 = half*4;
            for (int i = tidx; i < 1280; i += 256) {
                int tap = i >> 5, ci = (i >> 1) & 15, which = i & 1;
                const float* src = (which ? w2g : w1g) + tap*128 + ci*8 + o0;
                sW[i] = *(const float4*)src;
            }
            __syncthreads();

            uint64_t accA[4] = {0,0,0,0};
            uint64_t accB[4] = {0,0,0,0};

            for (int kh = 0; kh < 5; ++kh) {
                int hh = h + kh - 2;
                if ((unsigned)hh >= (unsigned)H) continue;
                const float* xrow = g_X + hh*16*XS;
                for (int kw = 0; kw < 8; ++kw) {
                    int cb0 = (q << 5) + kw*dil;
                    if (cb0 >= W) break;               // warp-uniform
                    const float* xp = xrow + cb0 + lane;
                    const ulonglong2* wp = (const ulonglong2*)(sW + (kh*8+kw)*32);
                    // prefetch all 16 x values (MLP batch, imm offsets)
                    float xs[16];
                    #pragma unroll
                    for (int ci = 0; ci < 16; ++ci) xs[ci] = xp[ci*XS];
                    #pragma unroll
                    for (int ci = 0; ci < 8; ++ci) {
                        uint64_t xv2 = pack2(xs[ci]);
                        ulonglong2 wv1 = wp[2*ci];
                        ulonglong2 wv2 = wp[2*ci+1];
                        fma2(accA[0], xv2, wv1.x); fma2(accA[1], xv2, wv1.y);
                        fma2(accA[2], xv2, wv2.x); fma2(accA[3], xv2, wv2.y);
                    }
                    #pragma unroll
                    for (int ci = 8; ci < 16; ++ci) {
                        uint64_t xv2 = pack2(xs[ci]);
                        ulonglong2 wv1 = wp[2*ci];
                        ulonglong2 wv2 = wp[2*ci+1];
                        fma2(accB[0], xv2, wv1.x); fma2(accB[1], xv2, wv1.y);
                        fma2(accB[2], xv2, wv2.x); fma2(accB[3], xv2, wv2.y);
                    }
                }
            }
            float y1[4], y2[4];
            {
                float2 a0 = unpack2(accA[0]), b0 = unpack2(accB[0]);
                float2 a1 = unpack2(accA[1]), b1v = unpack2(accB[1]);
                y1[0]=a0.x+b0.x; y1[1]=a0.y+b0.y; y1[2]=a1.x+b1v.x; y1[3]=a1.y+b1v.y;
                float2 a2 = unpack2(accA[2]), b2v = unpack2(accB[2]);
                float2 a3 = unpack2(accA[3]), b3 = unpack2(accB[3]);
                y2[0]=a2.x+b2v.x; y2[1]=a2.y+b2v.y; y2[2]=a3.x+b3.x; y2[3]=a3.y+b3.y;
            }
            #pragma unroll
            for (int j = 0; j < 4; ++j) {
                int oo = o0 + j;
                float g = dfh_tanh(y1[j] + __ldg(b1+oo)) * dfh_sig(y2[j] + __ldg(b2+oo));
                g_G[(h*8+oo)*GS + w] = g;
            }
        }
        gridbar(target);

        // ======== phase 2: z conv (8ch -> 8 of 16 outs) ========
        {
            const float* wzg = wza + layer*5120;
            const float* bz  = bza + layer*16;
            int o0 = half * 8;
            for (int i = tidx; i < 640; i += 256) {
                int tap = i >> 4, ci = (i >> 1) & 7, part = i & 1;
                sW[i] = *(const float4*)(wzg + tap*128 + ci*16 + o0 + part*4);
            }
            __syncthreads();

            uint64_t accA[4] = {0,0,0,0};
            uint64_t accB[4] = {0,0,0,0};

            for (int kh = 0; kh < 5; ++kh) {
                int hh = h + kh - 2;
                if ((unsigned)hh >= (unsigned)H) continue;
                const float* grow = g_G + hh*8*GS + w;
                #pragma unroll
                for (int kw = 0; kw < 8; ++kw) {
                    const float* xp = grow + kw;
                    const ulonglong2* wp = (const ulonglong2*)(sW + (kh*8+kw)*16);
                    float xs[8];
                    #pragma unroll
                    for (int ci = 0; ci < 8; ++ci) xs[ci] = xp[ci*GS];
                    #pragma unroll
                    for (int ci = 0; ci < 4; ++ci) {
                        uint64_t xv2 = pack2(xs[ci]);
                        ulonglong2 w01 = wp[2*ci];
                        ulonglong2 w23 = wp[2*ci+1];
                        fma2(accA[0], xv2, w01.x); fma2(accA[1], xv2, w01.y);
                        fma2(accA[2], xv2, w23.x); fma2(accA[3], xv2, w23.y);
                    }
                    #pragma unroll
                    for (int ci = 4; ci < 8; ++ci) {
                        uint64_t xv2 = pack2(xs[ci]);
                        ulonglong2 w01 = wp[2*ci];
                        ulonglong2 w23 = wp[2*ci+1];
                        fma2(accB[0], xv2, w01.x); fma2(accB[1], xv2, w01.y);
                        fma2(accB[2], xv2, w23.x); fma2(accB[3], xv2, w23.y);
                    }
                }
            }
            #pragma unroll
            for (int p = 0; p < 4; ++p) {
                float2 va = unpack2(accA[p]);
                float2 vb = unpack2(accB[p]);
                int oo = o0 + 2*p;
                float z0 = va.x + vb.x + __ldg(bz+oo);
                float z1 = va.y + vb.y + __ldg(bz+oo+1);
                int idx0 = (h*16+oo)*XS + w;
                int idx1 = idx0 + XS;
                g_SKIP[idx0] += z0;  g_X[idx0] += z0;
                g_SKIP[idx1] += z1;  g_X[idx1] += z1;
            }
        }
        gridbar(target);
    }
}

// ---------------- stage C1 ----------------
__global__ void k_c1()
{
    int t = blockIdx.x, f = blockIdx.y;     // 256 x 16
    __shared__ float vr[64], vi[64], tc[128], ts[128];
    int tid = threadIdx.x;                  // 128
    if (tid < 64) {
        int k = tid;
        float cr = g_SKIP[(t*16+f)*160 + 2*k];
        float ci = g_SKIP[(t*16+f)*160 + 2*k+1];
        cr = dfh_tanh(cr); ci = dfh_tanh(ci);
        float s = ((k==0)?0.5f:1.0f) * ((k&1)?-1.0f:1.0f);
        vr[k] = s*cr; vi[k] = s*ci;
    }
    {
        float sv, cv; sincospif((float)tid * (1.0f/64.0f), &sv, &cv);
        tc[tid] = cv; ts[tid] = sv;
    }
    __syncthreads();
    int m = tid;
    float acc = 0.0f;
    #pragma unroll 8
    for (int k = 0; k < 64; ++k) {
        int j = (k*m) & 127;
        acc += vr[k]*tc[j] + vi[k]*ts[j];
    }
    g_R2[(f*128+m)*NTc + t] = acc;
}

// ---------------- stage C2 ----------------
__global__ void k_c2(const float* __restrict__ times)
{
    int m = blockIdx.x, f = blockIdx.y;     // 128 x 16
    __shared__ float v[256], tc[256], ts[256];
    int tid = threadIdx.x;                  // 128
    v[tid]       = g_R2[(f*128+m)*NTc + tid];
    v[tid+128]   = g_R2[(f*128+m)*NTc + tid + 128];
    {
        float sv, cv;
        sincospif((float)tid * (1.0f/128.0f), &sv, &cv);        tc[tid] = cv;      ts[tid] = sv;
        sincospif((float)(tid+128) * (1.0f/128.0f), &sv, &cv);  tc[tid+128] = cv;  ts[tid+128] = sv;
    }
    __syncthreads();
    int k = tid;
    float zm = (k==0) ? 1.0f : ((fabsf(times[2*k]) > 0.0f) ? 1.0f : 0.0f);
    float scale = zm * ((k&1)?-1.0f:1.0f) * (1.0f/128.0f);
    float ar = 0.0f, ai = 0.0f;
    #pragma unroll 8
    for (int t = 0; t < 256; ++t) {
        int j = (t*k) & 255;
        ar += v[t]*tc[j];
        ai += v[t]*ts[j];
    }
    g_HINP[(m*16+f)*NTc + 2*k]   = scale*ar;
    g_HINP[(m*16+f)*NTc + 2*k+1] = scale*ai;
}

// ---------------- dense2 (16->16) ----------------
__global__ void k_dense2(const float* __restrict__ hw, const float* __restrict__ hb)
{
    int c = blockIdx.x;       // 128
    int t = threadIdx.x;      // 256
    float in[16];
    #pragma unroll
    for (int f = 0; f < 16; ++f) in[f] = g_HINP[(c*16+f)*NTc + t];
    #pragma unroll
    for (int o = 0; o < 16; ++o) {
        float acc = hb[o];
        #pragma unroll
        for (int f = 0; f < 16; ++f) acc += in[f]*hw[f*16+o];
        g_X[(c*16+o)*288 + t] = dfh_tanh(acc);
    }
}

// ---------------- stage D ----------------
__global__ void k_stageD()
{
    int c = blockIdx.x, g = blockIdx.y;     // 128 x 32
    __shared__ float hr[128], hi[128], tc[256], ts[256];
    int tid = threadIdx.x;                  // 256
    if (tid < 128) {
        int j = tid;
        float v0, v1;
        if (g < 16) {
            float a = g_SKIP[(c*16+g)*288 + 2*j];   v0 = dfh_tanh(a);
            float b = g_SKIP[(c*16+g)*288 + 2*j+1]; v1 = dfh_tanh(b);
        } else {
            v0 = g_HINP[(c*16+(g-16))*NTc + 2*j];
            v1 = g_HINP[(c*16+(g-16))*NTc + 2*j+1];
        }
        float s = ((j==0)?0.5f:1.0f) * ((j&1)?-1.0f:1.0f);
        hr[j] = s*v0; hi[j] = s*v1;
    }
    {
        float sv, cv; sincospif((float)tid * (1.0f/128.0f), &sv, &cv);
        tc[tid] = cv; ts[tid] = sv;
    }
    __syncthreads();
    int u = tid;
    float acc = 0.0f;
    #pragma unroll 8
    for (int j = 0; j < 128; ++j) {
        int idx = (j*u) & 255;
        acc += hr[j]*tc[idx] + hi[j]*ts[idx];
    }
    g_HFT[(g*128+c)*NTc + u] = acc;
}

// ---------------- fnorm ----------------
__global__ void k_fninit(){ g_FN = 0u; }

__global__ void k_fnred()
{
    int stride = gridDim.x*blockDim.x;
    float mx = 0.0f;
    for (int i = blockIdx.x*blockDim.x + threadIdx.x; i < 1048576; i += stride)
        mx = fmaxf(mx, fabsf(g_HFT[i]));
    #pragma unroll
    for (int o = 16; o; o >>= 1) mx = fmaxf(mx, __shfl_xor_sync(0xFFFFFFFFu, mx, o));
    __shared__ float sm[8];
    int lane = threadIdx.x & 31, warp = threadIdx.x >> 5;
    if (lane == 0) sm[warp] = mx;
    __syncthreads();
    if (warp == 0) {
        mx = (lane < 8) ? sm[lane] : 0.0f;
        #pragma unroll
        for (int o = 4; o; o >>= 1) mx = fmaxf(mx, __shfl_xor_sync(0xFFFFFFFFu, mx, o));
        if (lane == 0) atomicMax(&g_FN, __float_as_uint(mx));
    }
}

__global__ void k_refinit()
{
    float inv = 1.0f/__uint_as_float(g_FN);
    int c = blockIdx.x;     // 128
    int u = threadIdx.x;    // 256
    #pragma unroll 4
    for (int ch = 0; ch < 64; ++ch)
        g_RA[ch*RCH + c*RSTR + 4 + u] = g_HFT[(ch & 31)*32768 + c*256 + u] * inv;
}

// ---------------- FUSED refine conv: tt (tanh) + rr (relu) with x-prefetch ----------------
__global__ __launch_bounds__(256) void k_refconv(
    const float* __restrict__ Wt, const float* __restrict__ Wr,
    const float* __restrict__ Bt, const float* __restrict__ Br,
    int swap)
{
    const float* RIN  = swap ? g_RB : g_RA;
    float*       ROUT = swap ? g_RA : g_RB;
    int c    = blockIdx.x >> 2;
    int osel = blockIdx.x & 3;
    int o0   = osel * 8;
    int u    = threadIdx.x;       // 256
    __shared__ float4 sw[2304];   // per-kh stage: [kw(9)][ci(64)][4 float4] = 36KB

    uint64_t accT[4] = {0,0,0,0};
    uint64_t accR[4] = {0,0,0,0};

    for (int kh = 0; kh < 9; ++kh) {
        __syncthreads();
        for (int i = threadIdx.x; i < 2304; i += 256) {
            int kwci = i >> 2, part = i & 3;
            int koff = (kh*9 + (kwci >> 6))*2048 + (kwci & 63)*32 + o0;
            const float* src = (part < 2) ? (Wt + koff + part*4)
                                          : (Wr + koff + (part-2)*4);
            sw[i] = *(const float4*)src;
        }
        __syncthreads();

        int cc = c + kh - 4;
        if ((unsigned)cc >= 128u) continue;      // block-uniform
        const float* rowp = RIN + cc*RSTR + u;
        for (int kw = 0; kw < 9; ++kw) {
            const float* xp = rowp + kw;
            const ulonglong2* wp = (const ulonglong2*)(sw + kw*256);
            #pragma unroll 1
            for (int cg = 0; cg < 8; ++cg) {
                // prefetch 8 x values (MLP batch)
                float xs[8];
                #pragma unroll
                for (int j = 0; j < 8; ++j) xs[j] = __ldg(xp + (cg*8+j)*RCH);
                #pragma unroll
                for (int j = 0; j < 8; ++j) {
                    int ci = cg*8 + j;
                    uint64_t xv2 = pack2(xs[j]);
                    ulonglong2 t01 = wp[4*ci];
                    ulonglong2 t23 = wp[4*ci+1];
                    ulonglong2 r01 = wp[4*ci+2];
                    ulonglong2 r23 = wp[4*ci+3];
                    fma2(accT[0], xv2, t01.x); fma2(accT[1], xv2, t01.y);
                    fma2(accT[2], xv2, t23.x); fma2(accT[3], xv2, t23.y);
                    fma2(accR[0], xv2, r01.x); fma2(accR[1], xv2, r01.y);
                    fma2(accR[2], xv2, r23.x); fma2(accR[3], xv2, r23.y);
                }
            }
        }
    }
    int pos = c*RSTR + 4 + u;
    #pragma unroll
    for (int p = 0; p < 4; ++p) {
        float2 vt = unpack2(accT[p]);
        float2 vr = unpack2(accR[p]);
        float tv[2] = {vt.x, vt.y};
        float rv[2] = {vr.x, vr.y};
        #pragma unroll
        for (int s = 0; s < 2; ++s) {
            int k = o0 + 2*p + s;
            float t = dfh_tanh(tv[s] + __ldg(Bt + k));
            float rraw = rv[s] + __ldg(Br + k);
            float r = (rraw > 0.0f ? rraw : 0.0f)*0.98f + 0.02f*rraw;
            ROUT[k*RCH + pos]      = t + RIN[k*RCH + pos];
            ROUT[(32+k)*RCH + pos] = r + RIN[(32+k)*RCH + pos];
        }
    }
}

// ---------------- final dense (96 -> 2) ----------------
__global__ void k_final(const float* __restrict__ dw, const float* __restrict__ db,
                        float* __restrict__ out)
{
    int c = blockIdx.x;     // 128
    int u = threadIdx.x;    // 256
    int rpos = c*RSTR + 4 + u;
    int hpos = c*256 + u;
    float fn = __uint_as_float(g_FN);
    float a0 = __ldg(db), a1 = __ldg(db+1);
    #pragma unroll 8
    for (int p = 0; p < 64; ++p) {
        float v = g_RA[p*RCH + rpos] * fn;
        a0 += v*__ldg(dw + 2*p);
        a1 += v*__ldg(dw + 2*p + 1);
    }
    #pragma unroll 8
    for (int q = 0; q < 32; ++q) {
        float v = g_HFT[q*32768 + hpos];
        a0 += v*__ldg(dw + 2*(64+q));
        a1 += v*__ldg(dw + 2*(64+q) + 1);
    }
    out[hpos*2]     = a0;
    out[hpos*2 + 1] = a1/fn;
}

// ---------------- launch ----------------
extern "C" void kernel_launch(void* const* d_in, const int* in_sizes, int n_in,
                              void* d_out, int out_size)
{
    const float* times    = (const float*)d_in[0];
    const float* times_in = (const float*)d_in[1];
    const float* inp_nc   = (const float*)d_in[2];
    const float* inp_c    = (const float*)d_in[3];
    const float* cdw  = (const float*)d_in[4];
    const float* cdb  = (const float*)d_in[5];
    const float* cwy1 = (const float*)d_in[6];
    const float* cby1 = (const float*)d_in[7];
    const float* cwy2 = (const float*)d_in[8];
    const float* cby2 = (const float*)d_in[9];
    const float* cwz0 = (const float*)d_in[10];
    const float* cbz0 = (const float*)d_in[11];
    const float* hdw  = (const float*)d_in[12];
    const float* hdb  = (const float*)d_in[13];
    const float* hwy1 = (const float*)d_in[14];
    const float* hby1 = (const float*)d_in[15];
    const float* hwy2 = (const float*)d_in[16];
    const float* hby2 = (const float*)d_in[17];
    const float* hwz0 = (const float*)d_in[18];
    const float* hbz0 = (const float*)d_in[19];
    const float* rwr  = (const float*)d_in[20];
    const float* rbr  = (const float*)d_in[21];
    const float* rwt  = (const float*)d_in[22];
    const float* rbt  = (const float*)d_in[23];
    const float* dw   = (const float*)d_in[24];
    const float* db   = (const float*)d_in[25];
    float* out = (float*)d_out;

    // ---- fidnet 1: H=256, W=128, XS=160, GS=136 ----
    k_zero3<<<512,256>>>();           // also resets g_barcnt
    k_dense1<<<256,128>>>(inp_nc, inp_c, times, times_in, cdw, cdb);
    k_wave_all<256,128,160,136><<<256,256>>>(cwy1, cby1, cwy2, cby2, cwz0, cbz0);

    // ---- spectral glue ----
    k_c1<<<dim3(256,16),128>>>();
    k_c2<<<dim3(128,16),128>>>(times);

    // ---- fidnet 2: H=128, W=256, XS=288, GS=264 ----
    k_zero3<<<512,256>>>();           // resets g_barcnt again
    k_dense2<<<128,256>>>(hdw, hdb);
    k_wave_all<128,256,288,264><<<256,256>>>(hwy1, hby1, hwy2, hby2, hwz0, hbz0);

    // ---- hout_ft ----
    k_stageD<<<dim3(128,32),256>>>();

    // ---- fnorm + refine ----
    k_fninit<<<1,1>>>();
    k_fnred<<<256,256>>>();
    k_zeroref<<<512,256>>>();
    k_refinit<<<128,256>>>();
    for (int i = 0; i < 4; ++i) {
        k_refconv<<<512,256>>>(rwt + i*165888, rwr + i*165888,
                               rbt + i*32, rbr + i*32, i & 1);
    }

    // ---- final dense + output ----
    k_final<<<128,256>>>(dw, db, out);
}